// round 8
// baseline (speedup 1.0000x reference)
#include <cuda_runtime.h>
#include <cstdint>

#define NN     512
#define FIN    256
#define HF     256
#define NH     8
#define NF     32
#define NB     4
#define ITILE  32    // i-rows per item
#define GLS    36
#define GRS    36
#define ATS    36

typedef unsigned long long ull;

__device__ float g_scratch[(size_t)NB * NN * 512];

// ---- packed f32x2 helpers -------------------------------------------------
__device__ __forceinline__ ull pack2(float lo, float hi) {
    ull r; asm("mov.b64 %0, {%1, %2};" : "=l"(r) : "f"(lo), "f"(hi)); return r;
}
__device__ __forceinline__ void unpack2(ull v, float& lo, float& hi) {
    asm("mov.b64 {%0, %1}, %2;" : "=f"(lo), "=f"(hi) : "l"(v));
}
__device__ __forceinline__ ull add2(ull a, ull b) {
    ull r; asm("add.rn.f32x2 %0, %1, %2;" : "=l"(r) : "l"(a), "l"(b)); return r;
}
__device__ __forceinline__ ull fma2(ull a, ull b, ull c) {
    ull r; asm("fma.rn.f32x2 %0, %1, %2, %3;" : "=l"(r) : "l"(a), "l"(b), "l"(c)); return r;
}
__device__ __forceinline__ float ex2f(float x) {
    float r; asm("ex2.approx.f32 %0, %1;" : "=f"(r) : "f"(x)); return r;
}
#define L2E  1.4426950408889634f
#define LINR 1.5316455696f           // 0.605 / 0.395

// ---------------------------------------------------------------------------
// Kernel 1: fused GEMM  g_l = h @ W_l, g_r = h @ W_r
// ---------------------------------------------------------------------------
__global__ __launch_bounds__(256, 2)
void gemm_kernel(const float* __restrict__ A,
                 const float* __restrict__ WL,
                 const float* __restrict__ WR) {
    __shared__ ull   As2[2][16][64];
    __shared__ float Bs[2][16][68];

    const int nb = blockIdx.x;
    const float* Bm = (nb < 4) ? WL : WR;
    const int colOff = (nb < 4) ? 0 : 256;
    const int n0 = (nb & 3) * 64;
    const int m0 = blockIdx.y * 64;

    const int tid = threadIdx.x;
    const int tx = tid & 15;
    const int ty = tid >> 4;

    const int arow = tid >> 2;
    const int acol = (tid & 3) << 2;
    const int brow = tid >> 4;
    const int bcol = (tid & 15) << 2;

    const float* Aptr = A  + (size_t)(m0 + arow) * FIN + acol;
    const float* Bptr = Bm + (size_t)brow * HF + n0 + bcol;

    ull cc[4][2] = {};

    float4 av = *(const float4*)Aptr;
    float4 bv = *(const float4*)Bptr;

#pragma unroll 1
    for (int s = 0; s < 16; s++) {
        const int buf = s & 1;
        As2[buf][acol + 0][arow] = pack2(av.x, av.x);
        As2[buf][acol + 1][arow] = pack2(av.y, av.y);
        As2[buf][acol + 2][arow] = pack2(av.z, av.z);
        As2[buf][acol + 3][arow] = pack2(av.w, av.w);
        *(float4*)&Bs[buf][brow][bcol] = bv;
        __syncthreads();
        if (s < 15) {
            av = *(const float4*)(Aptr + (s + 1) * 16);
            bv = *(const float4*)(Bptr + (size_t)(s + 1) * 16 * HF);
        }
#pragma unroll
        for (int k = 0; k < 16; k++) {
            const ulonglong2 b2 = *(const ulonglong2*)&Bs[buf][k][tx * 4];
            const ulonglong2 aA = *(const ulonglong2*)&As2[buf][k][ty * 4];
            const ulonglong2 aB = *(const ulonglong2*)&As2[buf][k][ty * 4 + 2];
            cc[0][0] = fma2(aA.x, b2.x, cc[0][0]); cc[0][1] = fma2(aA.x, b2.y, cc[0][1]);
            cc[1][0] = fma2(aA.y, b2.x, cc[1][0]); cc[1][1] = fma2(aA.y, b2.y, cc[1][1]);
            cc[2][0] = fma2(aB.x, b2.x, cc[2][0]); cc[2][1] = fma2(aB.x, b2.y, cc[2][1]);
            cc[3][0] = fma2(aB.y, b2.x, cc[3][0]); cc[3][1] = fma2(aB.y, b2.y, cc[3][1]);
        }
        __syncthreads();
    }

    float* C = g_scratch + (size_t)m0 * 512 + colOff + n0;
#pragma unroll
    for (int r = 0; r < 4; r++) {
        ulonglong2 v; v.x = cc[r][0]; v.y = cc[r][1];
        *(ulonglong2*)(C + (size_t)(ty * 4 + r) * 512 + tx * 4) = v;
    }
}

// ---------------------------------------------------------------------------
// Kernel 2: persistent fused GATv2 attention.
// grid = 128 CTAs; CTA c owns (b,h) = c>>2 and i-blocks (c&3)*4 .. +3.
// Pass-1 abs folded into scalar FFMA |operand| modifiers (no LOP3 per elem).
// ---------------------------------------------------------------------------
#define OFF_GL   0
#define OFF_GR   (NN * GLS)                    // 18432
#define OFF_AT   (OFF_GR + NN * GRS)           // 36864
#define OFF_SL   (OFF_AT + NN * ATS)           // 55296
#define OFF_SR   (OFF_SL + NN)                 // 55808
#define OFF_SINV (OFF_SR + ITILE)              // 55840
#define OFF_MASK (OFF_SINV + ITILE)            // 55872
#define SMEM_FLOATS (OFF_MASK + ITILE * 16)    // 56384
#define SMEM_BYTES  (SMEM_FLOATS * 4)          // 225536

__global__ __launch_bounds__(256, 1)
void attn_kernel(const int* __restrict__ adj,
                 const float* __restrict__ attn_w,
                 float* __restrict__ out) {
    extern __shared__ float sm[];
    float* gl_s  = sm + OFF_GL;
    float* gr_s  = sm + OFF_GR;
    float* at_s  = sm + OFF_AT;
    float* Sl_s  = sm + OFF_SL;
    float* Sr_s  = sm + OFF_SR;
    float* sinv  = sm + OFF_SINV;
    unsigned* mask_s = (unsigned*)(sm + OFF_MASK);

    const int bh = blockIdx.x >> 2;            // 0..31
    const int b  = bh >> 3;
    const int h  = bh & 7;
    const int tid  = threadIdx.x;
    const int lane = tid & 31;
    const int warp = tid >> 5;                 // 0..7

    // scalar weights (sign kept; abs of the sum is pure)
    float wbs[32];
#pragma unroll
    for (int f = 0; f < 32; f++) wbs[f] = 0.395f * L2E * __ldg(attn_w + f);

    // ---- stage g_l / g_r slices once per CTA ----
    const float* gbase = g_scratch + ((size_t)b * NN) * 512 + h * NF;
#pragma unroll
    for (int it = 0; it < 16; it++) {
        const int idx = it * 256 + tid;
        const int j = idx >> 3;
        const int q = (idx & 7) << 2;
        const float* gp = gbase + (size_t)j * 512 + q;
        const float4 v = *(const float4*)gp;
        const float4 u = *(const float4*)(gp + 256);
        *(float4*)(gl_s + j * GLS + q) = v;
        *(float4*)(gr_s + j * GRS + q) = u;
    }
    __syncthreads();

    // ---- Sl[j] once per CTA ----
#pragma unroll
    for (int half = 0; half < 2; half++) {
        const int j = half * 256 + tid;
        const float* glp = gl_s + j * GLS;
        float acc = 0.f;
#pragma unroll
        for (int f = 0; f < 32; f++) acc = fmaf(wbs[f], glp[f], acc);
        Sl_s[j] = LINR * acc;
    }

    // =========================== item loop ===========================
#pragma unroll 1
    for (int item = 0; item < 4; item++) {
        const int blk = (blockIdx.x & 3) * 4 + item;
        const int i0 = blk * ITILE;

        // ---- adj -> bitmask ----
#pragma unroll
        for (int half = 0; half < 2; half++) {
            const int widx = half * 256 + tid;
            const int row = widx >> 4;
            const int chunk = widx & 15;
            const int4* ap = (const int4*)(adj + (size_t)(i0 + row) * NN + chunk * 32);
            unsigned w = 0;
#pragma unroll
            for (int k = 0; k < 8; k++) {
                const int4 v = ap[k];
                unsigned nib = (v.x != 0) | ((v.y != 0) << 1) |
                               ((v.z != 0) << 2) | ((v.w != 0) << 3);
                w |= nib << (4 * k);
            }
            mask_s[widx] = w;
        }

        // ---- Sr for these rows ----
        if (tid < ITILE) {
            const float* grp = gr_s + (i0 + tid) * GRS;
            float acc = 0.f;
#pragma unroll
            for (int f = 0; f < 32; f++) acc = fmaf(wbs[f], grp[f], acc);
            Sr_s[tid] = LINR * acc;
        }
        __syncthreads();

        // ---- pass 1: scores + exp2 + row sums (warp w: rows 4w..4w+3) ----
        {
            const int r0 = warp * 4;
            ull gri[4][16];
#pragma unroll
            for (int r = 0; r < 4; r++) {
                const ull* gp = (const ull*)(gr_s + (i0 + r0 + r) * GRS);
#pragma unroll
                for (int p = 0; p < 16; p++) gri[r][p] = gp[p];
            }
            float SrV[4], sum[4];
#pragma unroll
            for (int r = 0; r < 4; r++) { SrV[r] = Sr_s[r0 + r]; sum[r] = 0.f; }
            const unsigned* mr0 = mask_s + (r0 + 0) * 16;
            const unsigned* mr1 = mask_s + (r0 + 1) * 16;
            const unsigned* mr2 = mask_s + (r0 + 2) * 16;
            const unsigned* mr3 = mask_s + (r0 + 3) * 16;

#pragma unroll 2
            for (int jj = 0; jj < 16; jj++) {
                const int j = (jj << 5) + lane;
                const ulonglong2* glp = (const ulonglong2*)(gl_s + j * GLS);
                ulonglong2 gv = glp[0];
                const float slj = Sl_s[j];
                const unsigned w0 = mr0[jj], w1 = mr1[jj];
                const unsigned w2 = mr2[jj], w3 = mr3[jj];

                // two scalar acc chains per row
                float accA[4] = {0.f, 0.f, 0.f, 0.f};
                float accB[4] = {0.f, 0.f, 0.f, 0.f};
#pragma unroll
                for (int q = 0; q < 8; q++) {
                    ulonglong2 gvn;
                    if (q < 7) gvn = glp[q + 1];          // prefetch next
                    const int p0 = 2 * q, p1 = 2 * q + 1;
#pragma unroll
                    for (int r = 0; r < 4; r++) {
                        const ull t0 = add2(gv.x, gri[r][p0]);
                        const ull t1 = add2(gv.y, gri[r][p1]);
                        float a0, a1, b0, b1;
                        unpack2(t0, a0, a1);
                        unpack2(t1, b0, b1);
                        accA[r] = fmaf(wbs[4 * q + 0], fabsf(a0), accA[r]);
                        accB[r] = fmaf(wbs[4 * q + 1], fabsf(a1), accB[r]);
                        accA[r] = fmaf(wbs[4 * q + 2], fabsf(b0), accA[r]);
                        accB[r] = fmaf(wbs[4 * q + 3], fabsf(b1), accB[r]);
                    }
                    if (q < 7) gv = gvn;
                }
                float4 pv;
                {
                    const float p = ex2f(slj + SrV[0] + (accA[0] + accB[0]));
                    pv.x = ((w0 >> lane) & 1) ? p : 0.f; sum[0] += pv.x;
                }
                {
                    const float p = ex2f(slj + SrV[1] + (accA[1] + accB[1]));
                    pv.y = ((w1 >> lane) & 1) ? p : 0.f; sum[1] += pv.y;
                }
                {
                    const float p = ex2f(slj + SrV[2] + (accA[2] + accB[2]));
                    pv.z = ((w2 >> lane) & 1) ? p : 0.f; sum[2] += pv.z;
                }
                {
                    const float p = ex2f(slj + SrV[3] + (accA[3] + accB[3]));
                    pv.w = ((w3 >> lane) & 1) ? p : 0.f; sum[3] += pv.w;
                }
                *(float4*)(at_s + j * ATS + r0) = pv;
            }
#pragma unroll
            for (int o = 16; o; o >>= 1) {
#pragma unroll
                for (int r = 0; r < 4; r++)
                    sum[r] += __shfl_xor_sync(0xffffffffu, sum[r], o);
            }
            if (lane == 0) {
#pragma unroll
                for (int r = 0; r < 4; r++) sinv[r0 + r] = 1.0f / sum[r];
            }
        }
        __syncthreads();

        // ---- pass 2: partials into warp's own at_s slice ----
        {
            const int fq = tid & 7;
            const int ig = (tid >> 3) & 3;
            const int jq = warp;
            ull acc[4][4] = {};
            const int jbeg = jq * 64;
#pragma unroll 4
            for (int jo = 0; jo < 64; jo++) {
                const int j = jbeg + jo;
                const float4 g4 = *(const float4*)(gr_s + j * GRS + fq * 4);
                const ull pg0 = pack2(g4.x, g4.x);
                const ull pg1 = pack2(g4.y, g4.y);
                const ull pg2 = pack2(g4.z, g4.z);
                const ull pg3 = pack2(g4.w, g4.w);
                const ull* ap = (const ull*)(at_s + j * ATS + ig * 8);
#pragma unroll
                for (int p = 0; p < 4; p++) {
                    const ull a = ap[p];
                    acc[p][0] = fma2(a, pg0, acc[p][0]);
                    acc[p][1] = fma2(a, pg1, acc[p][1]);
                    acc[p][2] = fma2(a, pg2, acc[p][2]);
                    acc[p][3] = fma2(a, pg3, acc[p][3]);
                }
            }
            ull* part = (ull*)(at_s + jq * 64 * ATS);
#pragma unroll
            for (int p = 0; p < 4; p++) {
#pragma unroll
                for (int k = 0; k < 4; k++)
                    part[(ig * 4 + p) * 32 + fq * 4 + k] = acc[p][k];
            }
        }
        __syncthreads();

        // ---- final reduce over 8 slabs + scale + store ----
        {
            const int ip = tid >> 4;               // 0..15 (i-pair)
            const int f2 = (tid & 15) << 1;
            const ull* base = (const ull*)at_s;
            ull u0 = 0, u1 = 0;
#pragma unroll
            for (int q = 0; q < 8; q++) {
                const ull* slab = base + (size_t)q * (64 * ATS / 2);
                u0 = add2(u0, slab[ip * 32 + f2]);
                u1 = add2(u1, slab[ip * 32 + f2 + 1]);
            }
            float lo0, hi0, lo1, hi1;
            unpack2(u0, lo0, hi0);
            unpack2(u1, lo1, hi1);
            const float invA = sinv[2 * ip];
            const float invB = sinv[2 * ip + 1];
            float* opA = out + ((size_t)(b * NN + i0 + 2 * ip)) * HF + h * NF + f2;
            *(float2*)opA        = make_float2(lo0 * invA, lo1 * invA);
            *(float2*)(opA + HF) = make_float2(hi0 * invB, hi1 * invB);
        }
        __syncthreads();
    }
}

// ---------------------------------------------------------------------------
extern "C" void kernel_launch(void* const* d_in, const int* in_sizes, int n_in,
                              void* d_out, int out_size) {
    (void)in_sizes; (void)n_in; (void)out_size;
    const float* h      = (const float*)d_in[0];
    const int*   adj    = (const int*)  d_in[1];
    const float* W_l    = (const float*)d_in[2];
    const float* W_r    = (const float*)d_in[3];
    const float* attn_w = (const float*)d_in[4];
    float* out = (float*)d_out;

    cudaFuncSetAttribute(attn_kernel,
                         cudaFuncAttributeMaxDynamicSharedMemorySize, SMEM_BYTES);

    dim3 gg(8, 32);
    gemm_kernel<<<gg, 256>>>(h, W_l, W_r);

    attn_kernel<<<128, 256, SMEM_BYTES>>>(adj, attn_w, out);
}

// round 9
// speedup vs baseline: 1.5768x; 1.5768x over previous
#include <cuda_runtime.h>
#include <cstdint>

#define NN     512
#define FIN    256
#define HF     256
#define NH     8
#define NF     32
#define NB     4
#define ITILE  32    // i-rows per item
#define GLS    36
#define GRS    36
#define ATS    36

typedef unsigned long long ull;

__device__ float g_scratch[(size_t)NB * NN * 512];

// ---- packed f32x2 helpers -------------------------------------------------
__device__ __forceinline__ ull pack2(float lo, float hi) {
    ull r; asm("mov.b64 %0, {%1, %2};" : "=l"(r) : "f"(lo), "f"(hi)); return r;
}
__device__ __forceinline__ void unpack2(ull v, float& lo, float& hi) {
    asm("mov.b64 {%0, %1}, %2;" : "=f"(lo), "=f"(hi) : "l"(v));
}
__device__ __forceinline__ ull add2(ull a, ull b) {
    ull r; asm("add.rn.f32x2 %0, %1, %2;" : "=l"(r) : "l"(a), "l"(b)); return r;
}
__device__ __forceinline__ ull fma2(ull a, ull b, ull c) {
    ull r; asm("fma.rn.f32x2 %0, %1, %2, %3;" : "=l"(r) : "l"(a), "l"(b), "l"(c)); return r;
}
__device__ __forceinline__ float ex2f(float x) {
    float r; asm("ex2.approx.f32 %0, %1;" : "=f"(r) : "f"(x)); return r;
}
#define ABS2 0x7FFFFFFF7FFFFFFFULL
#define L2E  1.4426950408889634f
#define LINR 1.5316455696f           // 0.605 / 0.395

// ---------------------------------------------------------------------------
// Kernel 1: fused GEMM  g_l = h @ W_l, g_r = h @ W_r  (double-buffered smem,
// float As — the consistently-fastest variant across rounds)
// ---------------------------------------------------------------------------
__global__ __launch_bounds__(256, 2)
void gemm_kernel(const float* __restrict__ A,
                 const float* __restrict__ WL,
                 const float* __restrict__ WR) {
    __shared__ float As[2][16][64];
    __shared__ float Bs[2][16][68];

    const int nb = blockIdx.x;
    const float* Bm = (nb < 4) ? WL : WR;
    const int colOff = (nb < 4) ? 0 : 256;
    const int n0 = (nb & 3) * 64;
    const int m0 = blockIdx.y * 64;

    const int tid = threadIdx.x;
    const int tx = tid & 15;
    const int ty = tid >> 4;

    const int arow = tid >> 2;
    const int acol = (tid & 3) << 2;
    const int brow = tid >> 4;
    const int bcol = (tid & 15) << 2;

    const float* Aptr = A  + (size_t)(m0 + arow) * FIN + acol;
    const float* Bptr = Bm + (size_t)brow * HF + n0 + bcol;

    ull cc[4][2] = {};

    float4 av = *(const float4*)Aptr;
    float4 bv = *(const float4*)Bptr;

#pragma unroll 1
    for (int s = 0; s < 16; s++) {
        const int buf = s & 1;
        As[buf][acol + 0][arow] = av.x;
        As[buf][acol + 1][arow] = av.y;
        As[buf][acol + 2][arow] = av.z;
        As[buf][acol + 3][arow] = av.w;
        *(float4*)&Bs[buf][brow][bcol] = bv;
        __syncthreads();
        if (s < 15) {
            av = *(const float4*)(Aptr + (s + 1) * 16);
            bv = *(const float4*)(Bptr + (size_t)(s + 1) * 16 * HF);
        }
#pragma unroll
        for (int k = 0; k < 16; k++) {
            const ulonglong2 b2 = *(const ulonglong2*)&Bs[buf][k][tx * 4];
#pragma unroll
            for (int r = 0; r < 4; r++) {
                const float a = As[buf][k][ty * 4 + r];
                const ull pa = pack2(a, a);
                cc[r][0] = fma2(pa, b2.x, cc[r][0]);
                cc[r][1] = fma2(pa, b2.y, cc[r][1]);
            }
        }
        __syncthreads();
    }

    float* C = g_scratch + (size_t)m0 * 512 + colOff + n0;
#pragma unroll
    for (int r = 0; r < 4; r++) {
        ulonglong2 v; v.x = cc[r][0]; v.y = cc[r][1];
        *(ulonglong2*)(C + (size_t)(ty * 4 + r) * 512 + tx * 4) = v;
    }
}

// ---------------------------------------------------------------------------
// Kernel 2: persistent fused GATv2 attention (R7-proven form).
// grid = 128 CTAs; CTA c owns (b,h) = c>>2 and i-blocks (c&3)*4 .. +3.
// ---------------------------------------------------------------------------
#define OFF_GL   0
#define OFF_GR   (NN * GLS)                    // 18432
#define OFF_AT   (OFF_GR + NN * GRS)           // 36864
#define OFF_SL   (OFF_AT + NN * ATS)           // 55296
#define OFF_SR   (OFF_SL + NN)                 // 55808
#define OFF_SINV (OFF_SR + ITILE)              // 55840
#define OFF_MASK (OFF_SINV + ITILE)            // 55872
#define SMEM_FLOATS (OFF_MASK + ITILE * 16)    // 56384
#define SMEM_BYTES  (SMEM_FLOATS * 4)          // 225536

__global__ __launch_bounds__(256, 1)
void attn_kernel(const int* __restrict__ adj,
                 const float* __restrict__ attn_w,
                 float* __restrict__ out) {
    extern __shared__ float sm[];
    float* gl_s  = sm + OFF_GL;
    float* gr_s  = sm + OFF_GR;
    float* at_s  = sm + OFF_AT;
    float* Sl_s  = sm + OFF_SL;
    float* Sr_s  = sm + OFF_SR;
    float* sinv  = sm + OFF_SINV;
    unsigned* mask_s = (unsigned*)(sm + OFF_MASK);

    const int bh = blockIdx.x >> 2;            // 0..31
    const int b  = bh >> 3;
    const int h  = bh & 7;
    const int tid  = threadIdx.x;
    const int lane = tid & 31;
    const int warp = tid >> 5;                 // 0..7

    // packed weights: wb = 0.395 * log2(e) * w  (log2e folded -> raw ex2)
    ull wb2[16];
#pragma unroll
    for (int p = 0; p < 16; p++) {
        const float w0 = __ldg(attn_w + 2 * p);
        const float w1 = __ldg(attn_w + 2 * p + 1);
        wb2[p] = pack2(0.395f * L2E * w0, 0.395f * L2E * w1);
    }

    // ---- stage g_l / g_r slices once per CTA ----
    const float* gbase = g_scratch + ((size_t)b * NN) * 512 + h * NF;
#pragma unroll
    for (int it = 0; it < 16; it++) {
        const int idx = it * 256 + tid;
        const int j = idx >> 3;
        const int q = (idx & 7) << 2;
        const float* gp = gbase + (size_t)j * 512 + q;
        const float4 v = *(const float4*)gp;
        const float4 u = *(const float4*)(gp + 256);
        *(float4*)(gl_s + j * GLS + q) = v;
        *(float4*)(gr_s + j * GRS + q) = u;
    }
    __syncthreads();

    // ---- Sl[j] once per CTA ----
#pragma unroll
    for (int half = 0; half < 2; half++) {
        const int j = half * 256 + tid;
        const ull* glp = (const ull*)(gl_s + j * GLS);
        ull acc = 0;
#pragma unroll
        for (int p = 0; p < 16; p++) acc = fma2(wb2[p], glp[p], acc);
        float lo, hi; unpack2(acc, lo, hi);
        Sl_s[j] = LINR * (lo + hi);
    }

    // =========================== item loop ===========================
#pragma unroll 1
    for (int item = 0; item < 4; item++) {
        const int blk = (blockIdx.x & 3) * 4 + item;
        const int i0 = blk * ITILE;

        // ---- adj -> bitmask for these 32 rows ----
#pragma unroll
        for (int half = 0; half < 2; half++) {
            const int widx = half * 256 + tid;
            const int row = widx >> 4;
            const int chunk = widx & 15;
            const int4* ap = (const int4*)(adj + (size_t)(i0 + row) * NN + chunk * 32);
            unsigned w = 0;
#pragma unroll
            for (int k = 0; k < 8; k++) {
                const int4 v = ap[k];
                unsigned nib = (v.x != 0) | ((v.y != 0) << 1) |
                               ((v.z != 0) << 2) | ((v.w != 0) << 3);
                w |= nib << (4 * k);
            }
            mask_s[widx] = w;
        }

        // ---- Sr for these rows ----
        if (tid < ITILE) {
            const ull* grp = (const ull*)(gr_s + (i0 + tid) * GRS);
            ull acc = 0;
#pragma unroll
            for (int p = 0; p < 16; p++) acc = fma2(wb2[p], grp[p], acc);
            float lo, hi; unpack2(acc, lo, hi);
            Sr_s[tid] = LINR * (lo + hi);
        }
        __syncthreads();

        // ---- pass 1: scores + exp2 + row sums (warp w: rows 4w..4w+3) ----
        {
            const int r0 = warp * 4;
            ull gri[4][16];
#pragma unroll
            for (int r = 0; r < 4; r++) {
                const ull* gp = (const ull*)(gr_s + (i0 + r0 + r) * GRS);
#pragma unroll
                for (int p = 0; p < 16; p++) gri[r][p] = gp[p];
            }
            float SrV[4], sum[4];
#pragma unroll
            for (int r = 0; r < 4; r++) { SrV[r] = Sr_s[r0 + r]; sum[r] = 0.f; }
            const unsigned* mr0 = mask_s + (r0 + 0) * 16;
            const unsigned* mr1 = mask_s + (r0 + 1) * 16;
            const unsigned* mr2 = mask_s + (r0 + 2) * 16;
            const unsigned* mr3 = mask_s + (r0 + 3) * 16;

#pragma unroll 2
            for (int jj = 0; jj < 16; jj++) {
                const int j = (jj << 5) + lane;
                const ulonglong2* glp = (const ulonglong2*)(gl_s + j * GLS);
                ulonglong2 gv = glp[0];
                const float slj = Sl_s[j];
                const unsigned w0 = mr0[jj], w1 = mr1[jj];
                const unsigned w2 = mr2[jj], w3 = mr3[jj];

                ull acc0[4] = {0, 0, 0, 0};
                ull acc1[4] = {0, 0, 0, 0};
#pragma unroll
                for (int q = 0; q < 8; q++) {
                    ulonglong2 gvn;
                    if (q < 7) gvn = glp[q + 1];      // prefetch next
                    const int p0 = 2 * q, p1 = 2 * q + 1;
#pragma unroll
                    for (int r = 0; r < 4; r++) {
                        const ull t0 = add2(gv.x, gri[r][p0]);
                        const ull t1 = add2(gv.y, gri[r][p1]);
                        acc0[r] = fma2(wb2[p0], t0 & ABS2, acc0[r]);
                        acc1[r] = fma2(wb2[p1], t1 & ABS2, acc1[r]);
                    }
                    if (q < 7) gv = gvn;
                }
                float4 pv;
                {
                    float lo, hi; unpack2(add2(acc0[0], acc1[0]), lo, hi);
                    const float p = ex2f(slj + SrV[0] + (lo + hi));
                    pv.x = ((w0 >> lane) & 1) ? p : 0.f; sum[0] += pv.x;
                }
                {
                    float lo, hi; unpack2(add2(acc0[1], acc1[1]), lo, hi);
                    const float p = ex2f(slj + SrV[1] + (lo + hi));
                    pv.y = ((w1 >> lane) & 1) ? p : 0.f; sum[1] += pv.y;
                }
                {
                    float lo, hi; unpack2(add2(acc0[2], acc1[2]), lo, hi);
                    const float p = ex2f(slj + SrV[2] + (lo + hi));
                    pv.z = ((w2 >> lane) & 1) ? p : 0.f; sum[2] += pv.z;
                }
                {
                    float lo, hi; unpack2(add2(acc0[3], acc1[3]), lo, hi);
                    const float p = ex2f(slj + SrV[3] + (lo + hi));
                    pv.w = ((w3 >> lane) & 1) ? p : 0.f; sum[3] += pv.w;
                }
                *(float4*)(at_s + j * ATS + r0) = pv;
            }
#pragma unroll
            for (int o = 16; o; o >>= 1) {
#pragma unroll
                for (int r = 0; r < 4; r++)
                    sum[r] += __shfl_xor_sync(0xffffffffu, sum[r], o);
            }
            if (lane == 0) {
#pragma unroll
                for (int r = 0; r < 4; r++) sinv[r0 + r] = 1.0f / sum[r];
            }
        }
        __syncthreads();

        // ---- pass 2: partials into warp's own at_s slice ----
        {
            const int fq = tid & 7;
            const int ig = (tid >> 3) & 3;
            const int jq = warp;
            ull acc[4][4] = {};
            const int jbeg = jq * 64;
#pragma unroll 4
            for (int jo = 0; jo < 64; jo++) {
                const int j = jbeg + jo;
                const float4 g4 = *(const float4*)(gr_s + j * GRS + fq * 4);
                const ull pg0 = pack2(g4.x, g4.x);
                const ull pg1 = pack2(g4.y, g4.y);
                const ull pg2 = pack2(g4.z, g4.z);
                const ull pg3 = pack2(g4.w, g4.w);
                const ull* ap = (const ull*)(at_s + j * ATS + ig * 8);
#pragma unroll
                for (int p = 0; p < 4; p++) {
                    const ull a = ap[p];
                    acc[p][0] = fma2(a, pg0, acc[p][0]);
                    acc[p][1] = fma2(a, pg1, acc[p][1]);
                    acc[p][2] = fma2(a, pg2, acc[p][2]);
                    acc[p][3] = fma2(a, pg3, acc[p][3]);
                }
            }
            ull* part = (ull*)(at_s + jq * 64 * ATS);
#pragma unroll
            for (int p = 0; p < 4; p++) {
#pragma unroll
                for (int k = 0; k < 4; k++)
                    part[(ig * 4 + p) * 32 + fq * 4 + k] = acc[p][k];
            }
        }
        __syncthreads();

        // ---- final reduce over 8 slabs + scale + store ----
        {
            const int ip = tid >> 4;               // 0..15 (i-pair)
            const int f2 = (tid & 15) << 1;
            const ull* base = (const ull*)at_s;
            ull u0 = 0, u1 = 0;
#pragma unroll
            for (int q = 0; q < 8; q++) {
                const ull* slab = base + (size_t)q * (64 * ATS / 2);
                u0 = add2(u0, slab[ip * 32 + f2]);
                u1 = add2(u1, slab[ip * 32 + f2 + 1]);
            }
            float lo0, hi0, lo1, hi1;
            unpack2(u0, lo0, hi0);
            unpack2(u1, lo1, hi1);
            const float invA = sinv[2 * ip];
            const float invB = sinv[2 * ip + 1];
            float* opA = out + ((size_t)(b * NN + i0 + 2 * ip)) * HF + h * NF + f2;
            *(float2*)opA        = make_float2(lo0 * invA, lo1 * invA);
            *(float2*)(opA + HF) = make_float2(hi0 * invB, hi1 * invB);
        }
        __syncthreads();
    }
}

// ---------------------------------------------------------------------------
extern "C" void kernel_launch(void* const* d_in, const int* in_sizes, int n_in,
                              void* d_out, int out_size) {
    (void)in_sizes; (void)n_in; (void)out_size;
    const float* h      = (const float*)d_in[0];
    const int*   adj    = (const int*)  d_in[1];
    const float* W_l    = (const float*)d_in[2];
    const float* W_r    = (const float*)d_in[3];
    const float* attn_w = (const float*)d_in[4];
    float* out = (float*)d_out;

    cudaFuncSetAttribute(attn_kernel,
                         cudaFuncAttributeMaxDynamicSharedMemorySize, SMEM_BYTES);

    dim3 gg(8, 32);
    gemm_kernel<<<gg, 256>>>(h, W_l, W_r);

    attn_kernel<<<128, 256, SMEM_BYTES>>>(adj, attn_w, out);
}